// round 14
// baseline (speedup 1.0000x reference)
#include <cuda_runtime.h>
#include <cuda_bf16.h>
#include <stdint.h>

#define NH   3
#define D    256
#define E    768
#define B_   8
#define N_   2048
#define M_TOT (B_*N_)     /* 16384 */
#define BH_  (B_*NH)      /* 24    */

// ---------------------------------------------------------------------------
// Scratch (__device__ globals: allocation-guard-safe)
// ---------------------------------------------------------------------------
__device__ __align__(256) __nv_bfloat16 g_Xh[(size_t)M_TOT * E];
__device__ __align__(256) __nv_bfloat16 g_Xl[(size_t)M_TOT * E];
__device__ __align__(256) __nv_bfloat16 g_Wth[(size_t)9 * D * E];   // [th][d][e]
__device__ __align__(256) __nv_bfloat16 g_Wtl[(size_t)9 * D * E];
__device__ __align__(256) __nv_bfloat16 g_W0th[(size_t)E * E];      // [n][k]
__device__ __align__(256) __nv_bfloat16 g_W0tl[(size_t)E * E];
__device__ __align__(256) __nv_bfloat16 g_Qh[(size_t)BH_ * N_ * D];
__device__ __align__(256) __nv_bfloat16 g_Ql[(size_t)BH_ * N_ * D];
__device__ __align__(256) __nv_bfloat16 g_Kh[(size_t)BH_ * N_ * D];
__device__ __align__(256) __nv_bfloat16 g_Kl[(size_t)BH_ * N_ * D];
__device__ __align__(256) __nv_bfloat16 g_Vh[(size_t)BH_ * N_ * D];  // [bh][n][d]
__device__ __align__(256) __nv_bfloat16 g_Vl[(size_t)BH_ * N_ * D];
__device__ __align__(256) float         g_S [(size_t)BH_ * N_ * N_]; // E = exp(S/16)
__device__ __align__(256) __nv_bfloat16 g_atth[(size_t)M_TOT * E];
__device__ __align__(256) __nv_bfloat16 g_attl[(size_t)M_TOT * E];

// ---------------------------------------------------------------------------
// PTX helpers (base-target-safe: cp.async / ldmatrix / mma.sync only)
// ---------------------------------------------------------------------------
__device__ __forceinline__ uint32_t smem_u32(const void* p) {
    uint32_t a;
    asm("{ .reg .u64 t; cvta.to.shared.u64 t, %1; cvt.u32.u64 %0, t; }"
        : "=r"(a) : "l"(p));
    return a;
}

#define CP16(smem, gmem) \
    asm volatile("cp.async.cg.shared.global [%0], [%1], 16;" \
                 :: "r"((uint32_t)(smem)), "l"(gmem) : "memory")
#define CP_COMMIT() asm volatile("cp.async.commit_group;" ::: "memory")
#define CP_WAIT_0() asm volatile("cp.async.wait_group 0;" ::: "memory")
#define CP_WAIT_1() asm volatile("cp.async.wait_group 1;" ::: "memory")

#define LDSM_X4(r, addr) \
    asm volatile("ldmatrix.sync.aligned.m8n8.x4.shared.b16 {%0,%1,%2,%3}, [%4];" \
                 : "=r"((r)[0]), "=r"((r)[1]), "=r"((r)[2]), "=r"((r)[3]) \
                 : "r"(addr))
#define LDSM_X4_T(r, addr) \
    asm volatile("ldmatrix.sync.aligned.m8n8.x4.trans.shared.b16 {%0,%1,%2,%3}, [%4];" \
                 : "=r"((r)[0]), "=r"((r)[1]), "=r"((r)[2]), "=r"((r)[3]) \
                 : "r"(addr))

#define MMA16816(d, a, b0, b1) \
    asm volatile("mma.sync.aligned.m16n8k16.row.col.f32.bf16.bf16.f32 " \
                 "{%0,%1,%2,%3}, {%4,%5,%6,%7}, {%8,%9}, {%0,%1,%2,%3};" \
                 : "+f"((d)[0]), "+f"((d)[1]), "+f"((d)[2]), "+f"((d)[3]) \
                 : "r"((a)[0]), "r"((a)[1]), "r"((a)[2]), "r"((a)[3]), \
                   "r"(b0), "r"(b1))

#define LDS64(v, addr) \
    asm volatile("ld.shared.v2.f32 {%0,%1}, [%2];" \
                 : "=f"((v).x), "=f"((v).y) : "r"(addr))

// ---------------------------------------------------------------------------
// bf16 hi/lo helpers
// ---------------------------------------------------------------------------
__device__ __forceinline__ float bf16f(float a) {
    return __bfloat162float(__float2bfloat16(a));
}
__device__ __forceinline__ uint32_t pack2(float a, float b) {
    __nv_bfloat16 x = __float2bfloat16(a), y = __float2bfloat16(b);
    return (uint32_t)__bfloat16_as_ushort(x) | ((uint32_t)__bfloat16_as_ushort(y) << 16);
}
__device__ __forceinline__ void store_pair_hilo(__nv_bfloat16* dh, __nv_bfloat16* dl,
                                                size_t idx, float v0, float v1) {
    *reinterpret_cast<uint32_t*>(dh + idx) = pack2(v0, v1);
    *reinterpret_cast<uint32_t*>(dl + idx) = pack2(v0 - bf16f(v0), v1 - bf16f(v1));
}

// ---------------------------------------------------------------------------
// Generic GEMM engine (qkv / s / proj): C[128x128] += (Ah+Al)(Bh+Bl)^T
// (Al*Bl dropped).  K-chunk 32, 3-stage cp.async, 2 CTAs/SM.
// ---------------------------------------------------------------------------
#define ST_AL 8192u
#define ST_BH 16384u
#define ST_BL 24576u
#define STAGE_BYTES 32768u
#define GSMEM_BYTES (3 * STAGE_BYTES)   /* 98304 */

__device__ __forceinline__ void ld_stage(
    uint32_t st,
    const __nv_bfloat16* __restrict__ Ah, const __nv_bfloat16* __restrict__ Al,
    const __nv_bfloat16* __restrict__ Bh, const __nv_bfloat16* __restrict__ Bl,
    int lda, int ldb, int k0, int tid)
{
#pragma unroll
    for (int i = 0; i < 2; i++) {                       // A: 128 rows x 4 groups
        int f = tid + i * 256, r = f >> 2, g = f & 3;
        uint32_t sw = (uint32_t)(r * 64 + ((g ^ ((r >> 1) & 3)) << 4));
        CP16(st + sw,         Ah + (size_t)r * lda + k0 + g * 8);
        CP16(st + ST_AL + sw, Al + (size_t)r * lda + k0 + g * 8);
    }
#pragma unroll
    for (int i = 0; i < 2; i++) {                       // B: 128 rows x 4 groups
        int f = tid + i * 256, r = f >> 2, g = f & 3;
        uint32_t sw = (uint32_t)(r * 64 + ((g ^ ((r >> 1) & 3)) << 4));
        CP16(st + ST_BH + sw, Bh + (size_t)r * ldb + k0 + g * 8);
        CP16(st + ST_BL + sw, Bl + (size_t)r * ldb + k0 + g * 8);
    }
    CP_COMMIT();
}

__device__ __forceinline__ void gemm_ml(
    const __nv_bfloat16* Ah, const __nv_bfloat16* Al,
    const __nv_bfloat16* Bh, const __nv_bfloat16* Bl,
    int Kdim, int lda, int ldb, float (&acc)[4][4][4], char* smem)
{
    const uint32_t sb = smem_u32(smem);
    const int tid  = threadIdx.x;
    const int lane = tid & 31;
    const int wid  = tid >> 5;
    const int wm   = wid & 1;
    const int wn   = wid >> 1;

    const int rA   = wm * 64 + (lane & 15);
    const int qa   = lane >> 4;
    const int swA2 = (rA >> 1) & 3;
    const int rB   = wn * 32 + (lane & 7) + ((lane >> 4) << 3);
    const int qb   = (lane >> 3) & 1;
    const int swB2 = (rB >> 1) & 3;

    const int nc = Kdim >> 5;

    ld_stage(sb,               Ah, Al, Bh, Bl, lda, ldb, 0,  tid);
    ld_stage(sb + STAGE_BYTES, Ah, Al, Bh, Bl, lda, ldb, 32, tid);

    for (int c = 0; c < nc; c++) {
        const uint32_t st = sb + (uint32_t)(c % 3) * STAGE_BYTES;
        if (c + 1 < nc) { CP_WAIT_1(); } else { CP_WAIT_0(); }
        __syncthreads();
        if (c + 2 < nc)
            ld_stage(sb + (uint32_t)((c + 2) % 3) * STAGE_BYTES,
                     Ah, Al, Bh, Bl, lda, ldb, (c + 2) << 5, tid);

        const uint32_t stA = st, stAl = st + ST_AL;
        const uint32_t stB = st + ST_BH, stBl = st + ST_BL;

#pragma unroll
        for (int kk = 0; kk < 2; kk++) {
            uint32_t bh[2][4], bl[2][4];
            const uint32_t boff = (uint32_t)(((2 * kk + qb) ^ swB2) << 4);
#pragma unroll
            for (int nt2 = 0; nt2 < 2; nt2++) {
                uint32_t ro = (uint32_t)((rB + nt2 * 16) * 64) + boff;
                LDSM_X4(bh[nt2], stB  + ro);
                LDSM_X4(bl[nt2], stBl + ro);
            }
            const uint32_t aoff = (uint32_t)(((2 * kk + qa) ^ swA2) << 4);
#pragma unroll
            for (int mt = 0; mt < 4; mt++) {
                uint32_t ah[4], al[4];
                uint32_t ro = (uint32_t)((rA + mt * 16) * 64) + aoff;
                LDSM_X4(ah, stA  + ro);
                LDSM_X4(al, stAl + ro);
#pragma unroll
                for (int nt = 0; nt < 4; nt++) {
                    const int n2 = nt >> 1, hi = (nt & 1) * 2;
                    MMA16816(acc[mt][nt], ah, bh[n2][hi], bh[n2][hi + 1]);
                    MMA16816(acc[mt][nt], ah, bl[n2][hi], bl[n2][hi + 1]);
                    MMA16816(acc[mt][nt], al, bh[n2][hi], bh[n2][hi + 1]);
                }
            }
        }
    }
}

// ---------------------------------------------------------------------------
// Conversion kernels
// ---------------------------------------------------------------------------
__global__ void __launch_bounds__(256) convert_x_kernel(const float* __restrict__ x) {
    size_t i = (size_t)blockIdx.x * 256 + threadIdx.x;
    float4 v = reinterpret_cast<const float4*>(x)[i];
    uint2 h, l;
    h.x = pack2(v.x, v.y);  h.y = pack2(v.z, v.w);
    l.x = pack2(v.x - bf16f(v.x), v.y - bf16f(v.y));
    l.y = pack2(v.z - bf16f(v.z), v.w - bf16f(v.w));
    reinterpret_cast<uint2*>(g_Xh)[i] = h;
    reinterpret_cast<uint2*>(g_Xl)[i] = l;
}

__global__ void __launch_bounds__(256) convert_w_kernel(
    const float* __restrict__ Wq, const float* __restrict__ Wk,
    const float* __restrict__ Wv, const float* __restrict__ W0)
{
    size_t i = (size_t)blockIdx.x * 256 + threadIdx.x;
    if (i < (size_t)9 * D * E) {
        int th = (int)(i / (D * E));
        int r  = (int)(i % (D * E));
        int d  = r / E, e = r % E;
        int t = th / 3, h = th % 3;
        const float* W = (t == 0) ? Wq : (t == 1) ? Wk : Wv;
        float v = W[((size_t)h * E + e) * D + d];
        g_Wth[i] = __float2bfloat16(v);
        g_Wtl[i] = __float2bfloat16(v - bf16f(v));
    } else {
        size_t j = i - (size_t)9 * D * E;
        int n = (int)(j / E), k = (int)(j % E);
        float v = W0[(size_t)k * E + n];
        g_W0th[j] = __float2bfloat16(v);
        g_W0tl[j] = __float2bfloat16(v - bf16f(v));
    }
}

// ---------------------------------------------------------------------------
// 1) QKV: grid (2, 128, 9)
// ---------------------------------------------------------------------------
__global__ void __launch_bounds__(256, 2) qkv_tc_kernel(
    const float* __restrict__ bq, const float* __restrict__ bk,
    const float* __restrict__ bv)
{
    extern __shared__ char smem[];
    const int th = blockIdx.z;
    const int t = th / 3, h = th % 3;
    const int m0 = blockIdx.y * 128;
    const int n0 = blockIdx.x * 128;

    const __nv_bfloat16* Ah = g_Xh + (size_t)m0 * E;
    const __nv_bfloat16* Al = g_Xl + (size_t)m0 * E;
    const __nv_bfloat16* Bh = g_Wth + (size_t)th * D * E + (size_t)n0 * E;
    const __nv_bfloat16* Bl = g_Wtl + (size_t)th * D * E + (size_t)n0 * E;

    float acc[4][4][4] = {};
    gemm_ml(Ah, Al, Bh, Bl, E, E, E, acc, smem);

    const float* bias = ((t == 0) ? bq : (t == 1) ? bk : bv) + h * D;
    __nv_bfloat16* dh = (t == 0) ? g_Qh : (t == 1) ? g_Kh : g_Vh;
    __nv_bfloat16* dl = (t == 0) ? g_Ql : (t == 1) ? g_Kl : g_Vl;

    const int lane = threadIdx.x & 31, wid = threadIdx.x >> 5;
    const int wm = wid & 1, wn = wid >> 1;
#pragma unroll
    for (int mt = 0; mt < 4; mt++) {
        const int r0 = m0 + wm * 64 + mt * 16 + (lane >> 2);
#pragma unroll
        for (int nt = 0; nt < 4; nt++) {
            const int c = n0 + wn * 32 + nt * 8 + (lane & 3) * 2;
            const float bv0 = __ldg(bias + c), bv1 = __ldg(bias + c + 1);
#pragma unroll
            for (int hh = 0; hh < 2; hh++) {
                const int r = r0 + hh * 8;
                const int b = r >> 11, n = r & (N_ - 1);
                const size_t idx = ((size_t)((b * NH + h) * N_ + n)) * D + c;
                store_pair_hilo(dh, dl, idx,
                                acc[mt][nt][2 * hh + 0] + bv0,
                                acc[mt][nt][2 * hh + 1] + bv1);
            }
        }
    }
}

// ---------------------------------------------------------------------------
// 2) E = exp(Q K^T / 16) : grid (16, 16, 24) -> fp32 g_S
//    (no max subtraction: |s| <= |q||k|/16 ~ 5.3, exp safe in fp32)
// ---------------------------------------------------------------------------
__global__ void __launch_bounds__(256, 2) s_tc_kernel()
{
    extern __shared__ char smem[];
    const int bh = blockIdx.z;
    const int m0 = blockIdx.y * 128;
    const int n0 = blockIdx.x * 128;

    const __nv_bfloat16* Ah = g_Qh + ((size_t)bh * N_ + m0) * D;
    const __nv_bfloat16* Al = g_Ql + ((size_t)bh * N_ + m0) * D;
    const __nv_bfloat16* Bh = g_Kh + ((size_t)bh * N_ + n0) * D;
    const __nv_bfloat16* Bl = g_Kl + ((size_t)bh * N_ + n0) * D;

    float acc[4][4][4] = {};
    gemm_ml(Ah, Al, Bh, Bl, D, D, D, acc, smem);

    const int lane = threadIdx.x & 31, wid = threadIdx.x >> 5;
    const int wm = wid & 1, wn = wid >> 1;
#pragma unroll
    for (int mt = 0; mt < 4; mt++) {
        const int r0 = m0 + wm * 64 + mt * 16 + (lane >> 2);
#pragma unroll
        for (int nt = 0; nt < 4; nt++) {
            const int c = n0 + wn * 32 + nt * 8 + (lane & 3) * 2;
#pragma unroll
            for (int hh = 0; hh < 2; hh++) {
                const int r = r0 + hh * 8;
                float2 o;
                o.x = __expf(acc[mt][nt][2 * hh + 0] * 0.0625f);
                o.y = __expf(acc[mt][nt][2 * hh + 1] * 0.0625f);
                *reinterpret_cast<float2*>(g_S + ((size_t)bh * N_ + r) * N_ + c) = o;
            }
        }
    }
}

// ---------------------------------------------------------------------------
// 3) PV with in-register P fragments : grid (2, 16, 24).
// O = (E / rowsum(E)) @ V.  E fp32 staged in smem (16B-granule swizzle);
// each thread builds its mma A-fragments directly from float2 LDS reads
// (accumulator<->A-operand layout identity), splitting hi/lo in registers.
// Rowsums accumulated per-thread, butterfly-reduced over the 4-lane group.
// SMEM: E 3x16K | V 3x16K (hi 8K + lo 8K per slot) = 96KB; 2 CTAs/SM.
// ---------------------------------------------------------------------------
#define PVE_SMEM 98304

__global__ void __launch_bounds__(256, 2) pv_fused_kernel()
{
    extern __shared__ char smem[];
    const uint32_t sb = smem_u32(smem);
    const int bh = blockIdx.z;
    const int m0 = blockIdx.y * 128;
    const int n0 = blockIdx.x * 128;     // d-offset
    const int b = bh / 3, h = bh % 3;

    const int tid  = threadIdx.x;
    const int lane = tid & 31;
    const int wid  = tid >> 5;
    const int wm   = wid & 1;
    const int wn   = wid >> 1;

    // B (V, trans) addressing
    const int kB = (lane & 7) + (((lane >> 3) & 1) << 3);
    const int gB = (wn * 32 + ((lane >> 4) << 3)) >> 3;

    // E fragment addressing: row rl (+mt*16, +8), 16B granule (g ^ swk), 8B half
    const int rl  = wm * 64 + (lane >> 2);
    const int swk = lane >> 2;           // == row & 7 for all frag rows
    const int q2  = (lane & 3) >> 1;
    const int s8  = (lane & 1) * 8;

    const float* Ebase = g_S + ((size_t)bh * N_ + m0) * N_;
    const __nv_bfloat16* Vhb = g_Vh + (size_t)bh * N_ * D + n0;
    const __nv_bfloat16* Vlb = g_Vl + (size_t)bh * N_ * D + n0;

    const int nc = N_ >> 5;   // 64 chunks of 32 keys

    auto load_chunk = [&](int c) {
        const uint32_t es = sb + (uint32_t)(c % 3) * 16384u;
        const uint32_t vs = sb + 49152u + (uint32_t)(c % 3) * 16384u;
        const int k0 = c << 5;
#pragma unroll
        for (int i = 0; i < 4; i++) {                 // E: 128 rows x 8 granules
            int f = tid + i * 256, rr = f >> 3, cg = f & 7;
            uint32_t dst = es + (uint32_t)(rr * 128 + ((cg ^ (rr & 7)) << 4));
            CP16(dst, Ebase + (size_t)rr * N_ + k0 + cg * 4);
        }
#pragma unroll
        for (int i = 0; i < 2; i++) {                 // V: 32 k-rows x 16 groups
            int f = tid + i * 256, kr = f >> 4, g = f & 15;
            uint32_t sw = (uint32_t)(kr * 256 + ((g ^ (kr & 7)) << 4));
            CP16(vs + sw,         Vhb + (size_t)(k0 + kr) * D + g * 8);
            CP16(vs + 8192u + sw, Vlb + (size_t)(k0 + kr) * D + g * 8);
        }
        CP_COMMIT();
    };

    load_chunk(0);
    load_chunk(1);

    float acc[4][4][4] = {};
    float rs0[4] = {}, rs1[4] = {};

    for (int c = 0; c < nc; c++) {
        if (c + 1 < nc) { CP_WAIT_1(); } else { CP_WAIT_0(); }
        __syncthreads();
        if (c + 2 < nc) load_chunk(c + 2);

        const uint32_t es   = sb + (uint32_t)(c % 3) * 16384u;
        const uint32_t stB  = sb + 49152u + (uint32_t)(c % 3) * 16384u;
        const uint32_t stBl = stB + 8192u;

#pragma unroll
        for (int kk = 0; kk < 2; kk++) {
            uint32_t bhf[2][4], blf[2][4];
            const int k = kk * 16 + kB;
#pragma unroll
            for (int nt2 = 0; nt2 < 2; nt2++) {
                uint32_t ro = (uint32_t)(k * 256 + (((gB + nt2 * 2) ^ (k & 7)) << 4));
                LDSM_X4_T(bhf[nt2], stB  + ro);
                LDSM_X4_T(blf[nt2], stBl + ro);
            }
            const int g0 = 4 * kk + q2;      // granule of cols kk*16 + (lane&3)*2
            const int g1 = g0 + 2;           // +8 cols
            const uint32_t o0 = (uint32_t)(((g0 ^ swk) << 4) + s8);
            const uint32_t o1 = (uint32_t)(((g1 ^ swk) << 4) + s8);
#pragma unroll
            for (int mt = 0; mt < 4; mt++) {
                const uint32_t row  = es + (uint32_t)((rl + mt * 16) * 128);
                const uint32_t row8 = row + 1024u;
                float2 e00, e01, e10, e11;
                LDS64(e00, row  + o0);
                LDS64(e01, row  + o1);
                LDS64(e10, row8 + o0);
                LDS64(e11, row8 + o1);
                rs0[mt] += (e00.x + e00.y) + (e01.x + e01.y);
                rs1[mt] += (e10.x + e10.y) + (e11.x + e11.y);
                // A-frags: a0=(r,k0-7) a1=(r+8,k0-7) a2=(r,k8-15) a3=(r+8,k8-15)
                uint32_t ahf[4], alf[4];
#define SPLIT_PAIR(e, ho, lo_) {                                        \
    uint32_t _ux = __float_as_uint((e).x), _uy = __float_as_uint((e).y);\
    ho = (_ux >> 16) | (_uy & 0xffff0000u);                             \
    float _lx = (e).x - __uint_as_float(_ux & 0xffff0000u);             \
    float _ly = (e).y - __uint_as_float(_uy & 0xffff0000u);             \
    lo_ = pack2(_lx, _ly); }
                SPLIT_PAIR(e00, ahf[0], alf[0]);
                SPLIT_PAIR(e10, ahf[1], alf[1]);
                SPLIT_PAIR(e01, ahf[2], alf[2]);
                SPLIT_PAIR(e11, ahf[3], alf[3]);
#undef SPLIT_PAIR
#pragma unroll
                for (int nt = 0; nt < 4; nt++) {
                    const int n2 = nt >> 1, hi = (nt & 1) * 2;
                    MMA16816(acc[mt][nt], ahf, bhf[n2][hi], bhf[n2][hi + 1]);
                    MMA16816(acc[mt][nt], ahf, blf[n2][hi], blf[n2][hi + 1]);
                    MMA16816(acc[mt][nt], alf, bhf[n2][hi], bhf[n2][hi + 1]);
                }
            }
        }
    }

    // rowsum butterfly over the 4-lane group (disjoint col subsets), normalize
#pragma unroll
    for (int mt = 0; mt < 4; mt++) {
        float s0 = rs0[mt], s1 = rs1[mt];
        s0 += __shfl_xor_sync(0xffffffffu, s0, 1);
        s0 += __shfl_xor_sync(0xffffffffu, s0, 2);
        s1 += __shfl_xor_sync(0xffffffffu, s1, 1);
        s1 += __shfl_xor_sync(0xffffffffu, s1, 2);
        const float inv0 = 1.0f / s0, inv1 = 1.0f / s1;
        const int r0 = m0 + wm * 64 + mt * 16 + (lane >> 2);
#pragma unroll
        for (int nt = 0; nt < 4; nt++) {
            const int cc = n0 + wn * 32 + nt * 8 + (lane & 3) * 2;
#pragma unroll
            for (int hh = 0; hh < 2; hh++) {
                const int r = r0 + hh * 8;
                const float inv = hh ? inv1 : inv0;
                const size_t idx = ((size_t)(b * N_ + r)) * E + h * D + cc;
                store_pair_hilo(g_atth, g_attl, idx,
                                acc[mt][nt][2 * hh + 0] * inv,
                                acc[mt][nt][2 * hh + 1] * inv);
            }
        }
    }
}

// ---------------------------------------------------------------------------
// 4) out = att @ W0 + b0 : grid (6, 128) -> fp32 out
// ---------------------------------------------------------------------------
__global__ void __launch_bounds__(256, 2) proj_tc_kernel(
    const float* __restrict__ b0, float* __restrict__ out)
{
    extern __shared__ char smem[];
    const int m0 = blockIdx.y * 128;
    const int n0 = blockIdx.x * 128;

    const __nv_bfloat16* Ah = g_atth + (size_t)m0 * E;
    const __nv_bfloat16* Al = g_attl + (size_t)m0 * E;
    const __nv_bfloat16* Bh = g_W0th + (size_t)n0 * E;
    const __nv_bfloat16* Bl = g_W0tl + (size_t)n0 * E;

    float acc[4][4][4] = {};
    gemm_ml(Ah, Al, Bh, Bl, E, E, E, acc, smem);

    const int lane = threadIdx.x & 31, wid = threadIdx.x >> 5;
    const int wm = wid & 1, wn = wid >> 1;
#pragma unroll
    for (int mt = 0; mt < 4; mt++) {
        const int r0 = m0 + wm * 64 + mt * 16 + (lane >> 2);
#pragma unroll
        for (int nt = 0; nt < 4; nt++) {
            const int c = n0 + wn * 32 + nt * 8 + (lane & 3) * 2;
            const float bv0 = __ldg(b0 + c), bv1 = __ldg(b0 + c + 1);
#pragma unroll
            for (int hh = 0; hh < 2; hh++) {
                const int r = r0 + hh * 8;
                float2 o;
                o.x = acc[mt][nt][2 * hh + 0] + bv0;
                o.y = acc[mt][nt][2 * hh + 1] + bv1;
                *reinterpret_cast<float2*>(out + (size_t)r * E + c) = o;
            }
        }
    }
}

// ---------------------------------------------------------------------------
extern "C" void kernel_launch(void* const* d_in, const int* in_sizes, int n_in,
                              void* d_out, int out_size)
{
    const float* x  = (const float*)d_in[0];
    const float* Wq = (const float*)d_in[1];
    const float* bq = (const float*)d_in[2];
    const float* Wk = (const float*)d_in[3];
    const float* bk = (const float*)d_in[4];
    const float* Wv = (const float*)d_in[5];
    const float* bv = (const float*)d_in[6];
    const float* W0 = (const float*)d_in[7];
    const float* b0 = (const float*)d_in[8];
    float* out = (float*)d_out;

    cudaFuncSetAttribute(qkv_tc_kernel,   cudaFuncAttributeMaxDynamicSharedMemorySize, GSMEM_BYTES);
    cudaFuncSetAttribute(s_tc_kernel,     cudaFuncAttributeMaxDynamicSharedMemorySize, GSMEM_BYTES);
    cudaFuncSetAttribute(pv_fused_kernel, cudaFuncAttributeMaxDynamicSharedMemorySize, PVE_SMEM);
    cudaFuncSetAttribute(proj_tc_kernel,  cudaFuncAttributeMaxDynamicSharedMemorySize, GSMEM_BYTES);

    convert_x_kernel<<<(M_TOT * E / 4) / 256, 256>>>(x);
    convert_w_kernel<<<(9 * D * E + E * E) / 256, 256>>>(Wq, Wk, Wv, W0);

    qkv_tc_kernel<<<dim3(2, 128, 9), 256, GSMEM_BYTES>>>(bq, bk, bv);
    s_tc_kernel<<<dim3(16, 16, BH_), 256, GSMEM_BYTES>>>();
    pv_fused_kernel<<<dim3(2, 16, BH_), 256, PVE_SMEM>>>();
    proj_tc_kernel<<<dim3(6, 128), 256, GSMEM_BYTES>>>(b0, out);
}

// round 15
// speedup vs baseline: 1.0439x; 1.0439x over previous
#include <cuda_runtime.h>
#include <cuda_bf16.h>
#include <stdint.h>

#define NH   3
#define D    256
#define E    768
#define B_   8
#define N_   2048
#define M_TOT (B_*N_)     /* 16384 */
#define BH_  (B_*NH)      /* 24    */

// ---------------------------------------------------------------------------
// Scratch (__device__ globals: allocation-guard-safe)
// ---------------------------------------------------------------------------
__device__ __align__(256) __nv_bfloat16 g_Xh[(size_t)M_TOT * E];
__device__ __align__(256) __nv_bfloat16 g_Xl[(size_t)M_TOT * E];
__device__ __align__(256) __nv_bfloat16 g_Wth[(size_t)9 * D * E];   // [th][d][e]
__device__ __align__(256) __nv_bfloat16 g_Wtl[(size_t)9 * D * E];
__device__ __align__(256) __nv_bfloat16 g_W0th[(size_t)E * E];      // [n][k]
__device__ __align__(256) __nv_bfloat16 g_W0tl[(size_t)E * E];
__device__ __align__(256) __nv_bfloat16 g_Qh[(size_t)BH_ * N_ * D];
__device__ __align__(256) __nv_bfloat16 g_Ql[(size_t)BH_ * N_ * D];
__device__ __align__(256) __nv_bfloat16 g_Kh[(size_t)BH_ * N_ * D];
__device__ __align__(256) __nv_bfloat16 g_Kl[(size_t)BH_ * N_ * D];
__device__ __align__(256) __nv_bfloat16 g_Vh[(size_t)BH_ * N_ * D];  // [bh][n][d]
__device__ __align__(256) __nv_bfloat16 g_Vl[(size_t)BH_ * N_ * D];
__device__ __align__(256) float         g_S [(size_t)BH_ * N_ * N_]; // E = exp(S/16)
__device__ __align__(256) __nv_bfloat16 g_atth[(size_t)M_TOT * E];
__device__ __align__(256) __nv_bfloat16 g_attl[(size_t)M_TOT * E];

// ---------------------------------------------------------------------------
// PTX helpers (base-target-safe: cp.async / ldmatrix / mma.sync only)
// ---------------------------------------------------------------------------
__device__ __forceinline__ uint32_t smem_u32(const void* p) {
    uint32_t a;
    asm("{ .reg .u64 t; cvta.to.shared.u64 t, %1; cvt.u32.u64 %0, t; }"
        : "=r"(a) : "l"(p));
    return a;
}

#define CP16(smem, gmem) \
    asm volatile("cp.async.cg.shared.global [%0], [%1], 16;" \
                 :: "r"((uint32_t)(smem)), "l"(gmem) : "memory")
#define CP_COMMIT() asm volatile("cp.async.commit_group;" ::: "memory")
#define CP_WAIT_0() asm volatile("cp.async.wait_group 0;" ::: "memory")
#define CP_WAIT_1() asm volatile("cp.async.wait_group 1;" ::: "memory")

#define LDSM_X4(r, addr) \
    asm volatile("ldmatrix.sync.aligned.m8n8.x4.shared.b16 {%0,%1,%2,%3}, [%4];" \
                 : "=r"((r)[0]), "=r"((r)[1]), "=r"((r)[2]), "=r"((r)[3]) \
                 : "r"(addr))
#define LDSM_X4_T(r, addr) \
    asm volatile("ldmatrix.sync.aligned.m8n8.x4.trans.shared.b16 {%0,%1,%2,%3}, [%4];" \
                 : "=r"((r)[0]), "=r"((r)[1]), "=r"((r)[2]), "=r"((r)[3]) \
                 : "r"(addr))

#define MMA16816(d, a, b0, b1) \
    asm volatile("mma.sync.aligned.m16n8k16.row.col.f32.bf16.bf16.f32 " \
                 "{%0,%1,%2,%3}, {%4,%5,%6,%7}, {%8,%9}, {%0,%1,%2,%3};" \
                 : "+f"((d)[0]), "+f"((d)[1]), "+f"((d)[2]), "+f"((d)[3]) \
                 : "r"((a)[0]), "r"((a)[1]), "r"((a)[2]), "r"((a)[3]), \
                   "r"(b0), "r"(b1))

// ---------------------------------------------------------------------------
// bf16 hi/lo helpers
// ---------------------------------------------------------------------------
__device__ __forceinline__ float bf16f(float a) {
    return __bfloat162float(__float2bfloat16(a));
}
__device__ __forceinline__ uint32_t pack2(float a, float b) {
    __nv_bfloat16 x = __float2bfloat16(a), y = __float2bfloat16(b);
    return (uint32_t)__bfloat16_as_ushort(x) | ((uint32_t)__bfloat16_as_ushort(y) << 16);
}
__device__ __forceinline__ void store_pair_hilo(__nv_bfloat16* dh, __nv_bfloat16* dl,
                                                size_t idx, float v0, float v1) {
    *reinterpret_cast<uint32_t*>(dh + idx) = pack2(v0, v1);
    *reinterpret_cast<uint32_t*>(dl + idx) = pack2(v0 - bf16f(v0), v1 - bf16f(v1));
}

// ---------------------------------------------------------------------------
// Generic GEMM engine (qkv / s / proj): C[128x128] += (Ah+Al)(Bh+Bl)^T
// (Al*Bl dropped).  K-chunk 32, 3-stage cp.async, 2 CTAs/SM.
// ---------------------------------------------------------------------------
#define ST_AL 8192u
#define ST_BH 16384u
#define ST_BL 24576u
#define STAGE_BYTES 32768u
#define GSMEM_BYTES (3 * STAGE_BYTES)   /* 98304 */

__device__ __forceinline__ void ld_stage(
    uint32_t st,
    const __nv_bfloat16* __restrict__ Ah, const __nv_bfloat16* __restrict__ Al,
    const __nv_bfloat16* __restrict__ Bh, const __nv_bfloat16* __restrict__ Bl,
    int lda, int ldb, int k0, int tid)
{
#pragma unroll
    for (int i = 0; i < 2; i++) {                       // A: 128 rows x 4 groups
        int f = tid + i * 256, r = f >> 2, g = f & 3;
        uint32_t sw = (uint32_t)(r * 64 + ((g ^ ((r >> 1) & 3)) << 4));
        CP16(st + sw,         Ah + (size_t)r * lda + k0 + g * 8);
        CP16(st + ST_AL + sw, Al + (size_t)r * lda + k0 + g * 8);
    }
#pragma unroll
    for (int i = 0; i < 2; i++) {                       // B: 128 rows x 4 groups
        int f = tid + i * 256, r = f >> 2, g = f & 3;
        uint32_t sw = (uint32_t)(r * 64 + ((g ^ ((r >> 1) & 3)) << 4));
        CP16(st + ST_BH + sw, Bh + (size_t)r * ldb + k0 + g * 8);
        CP16(st + ST_BL + sw, Bl + (size_t)r * ldb + k0 + g * 8);
    }
    CP_COMMIT();
}

__device__ __forceinline__ void gemm_ml(
    const __nv_bfloat16* Ah, const __nv_bfloat16* Al,
    const __nv_bfloat16* Bh, const __nv_bfloat16* Bl,
    int Kdim, int lda, int ldb, float (&acc)[4][4][4], char* smem)
{
    const uint32_t sb = smem_u32(smem);
    const int tid  = threadIdx.x;
    const int lane = tid & 31;
    const int wid  = tid >> 5;
    const int wm   = wid & 1;
    const int wn   = wid >> 1;

    const int rA   = wm * 64 + (lane & 15);
    const int qa   = lane >> 4;
    const int swA2 = (rA >> 1) & 3;
    const int rB   = wn * 32 + (lane & 7) + ((lane >> 4) << 3);
    const int qb   = (lane >> 3) & 1;
    const int swB2 = (rB >> 1) & 3;

    const int nc = Kdim >> 5;

    ld_stage(sb,               Ah, Al, Bh, Bl, lda, ldb, 0,  tid);
    ld_stage(sb + STAGE_BYTES, Ah, Al, Bh, Bl, lda, ldb, 32, tid);

    for (int c = 0; c < nc; c++) {
        const uint32_t st = sb + (uint32_t)(c % 3) * STAGE_BYTES;
        if (c + 1 < nc) { CP_WAIT_1(); } else { CP_WAIT_0(); }
        __syncthreads();
        if (c + 2 < nc)
            ld_stage(sb + (uint32_t)((c + 2) % 3) * STAGE_BYTES,
                     Ah, Al, Bh, Bl, lda, ldb, (c + 2) << 5, tid);

        const uint32_t stA = st, stAl = st + ST_AL;
        const uint32_t stB = st + ST_BH, stBl = st + ST_BL;

#pragma unroll
        for (int kk = 0; kk < 2; kk++) {
            uint32_t bh[2][4], bl[2][4];
            const uint32_t boff = (uint32_t)(((2 * kk + qb) ^ swB2) << 4);
#pragma unroll
            for (int nt2 = 0; nt2 < 2; nt2++) {
                uint32_t ro = (uint32_t)((rB + nt2 * 16) * 64) + boff;
                LDSM_X4(bh[nt2], stB  + ro);
                LDSM_X4(bl[nt2], stBl + ro);
            }
            const uint32_t aoff = (uint32_t)(((2 * kk + qa) ^ swA2) << 4);
#pragma unroll
            for (int mt = 0; mt < 4; mt++) {
                uint32_t ah[4], al[4];
                uint32_t ro = (uint32_t)((rA + mt * 16) * 64) + aoff;
                LDSM_X4(ah, stA  + ro);
                LDSM_X4(al, stAl + ro);
#pragma unroll
                for (int nt = 0; nt < 4; nt++) {
                    const int n2 = nt >> 1, hi = (nt & 1) * 2;
                    MMA16816(acc[mt][nt], ah, bh[n2][hi], bh[n2][hi + 1]);
                    MMA16816(acc[mt][nt], ah, bl[n2][hi], bl[n2][hi + 1]);
                    MMA16816(acc[mt][nt], al, bh[n2][hi], bh[n2][hi + 1]);
                }
            }
        }
    }
}

// ---------------------------------------------------------------------------
// Conversion kernels
// ---------------------------------------------------------------------------
__global__ void __launch_bounds__(256) convert_x_kernel(const float* __restrict__ x) {
    size_t i = (size_t)blockIdx.x * 256 + threadIdx.x;
    float4 v = reinterpret_cast<const float4*>(x)[i];
    uint2 h, l;
    h.x = pack2(v.x, v.y);  h.y = pack2(v.z, v.w);
    l.x = pack2(v.x - bf16f(v.x), v.y - bf16f(v.y));
    l.y = pack2(v.z - bf16f(v.z), v.w - bf16f(v.w));
    reinterpret_cast<uint2*>(g_Xh)[i] = h;
    reinterpret_cast<uint2*>(g_Xl)[i] = l;
}

__global__ void __launch_bounds__(256) convert_w_kernel(
    const float* __restrict__ Wq, const float* __restrict__ Wk,
    const float* __restrict__ Wv, const float* __restrict__ W0)
{
    size_t i = (size_t)blockIdx.x * 256 + threadIdx.x;
    if (i < (size_t)9 * D * E) {
        int th = (int)(i / (D * E));
        int r  = (int)(i % (D * E));
        int d  = r / E, e = r % E;
        int t = th / 3, h = th % 3;
        const float* W = (t == 0) ? Wq : (t == 1) ? Wk : Wv;
        float v = W[((size_t)h * E + e) * D + d];
        g_Wth[i] = __float2bfloat16(v);
        g_Wtl[i] = __float2bfloat16(v - bf16f(v));
    } else {
        size_t j = i - (size_t)9 * D * E;
        int n = (int)(j / E), k = (int)(j % E);
        float v = W0[(size_t)k * E + n];
        g_W0th[j] = __float2bfloat16(v);
        g_W0tl[j] = __float2bfloat16(v - bf16f(v));
    }
}

// ---------------------------------------------------------------------------
// 1) QKV: grid (2, 128, 9)
// ---------------------------------------------------------------------------
__global__ void __launch_bounds__(256, 2) qkv_tc_kernel(
    const float* __restrict__ bq, const float* __restrict__ bk,
    const float* __restrict__ bv)
{
    extern __shared__ char smem[];
    const int th = blockIdx.z;
    const int t = th / 3, h = th % 3;
    const int m0 = blockIdx.y * 128;
    const int n0 = blockIdx.x * 128;

    const __nv_bfloat16* Ah = g_Xh + (size_t)m0 * E;
    const __nv_bfloat16* Al = g_Xl + (size_t)m0 * E;
    const __nv_bfloat16* Bh = g_Wth + (size_t)th * D * E + (size_t)n0 * E;
    const __nv_bfloat16* Bl = g_Wtl + (size_t)th * D * E + (size_t)n0 * E;

    float acc[4][4][4] = {};
    gemm_ml(Ah, Al, Bh, Bl, E, E, E, acc, smem);

    const float* bias = ((t == 0) ? bq : (t == 1) ? bk : bv) + h * D;
    __nv_bfloat16* dh = (t == 0) ? g_Qh : (t == 1) ? g_Kh : g_Vh;
    __nv_bfloat16* dl = (t == 0) ? g_Ql : (t == 1) ? g_Kl : g_Vl;

    const int lane = threadIdx.x & 31, wid = threadIdx.x >> 5;
    const int wm = wid & 1, wn = wid >> 1;
#pragma unroll
    for (int mt = 0; mt < 4; mt++) {
        const int r0 = m0 + wm * 64 + mt * 16 + (lane >> 2);
#pragma unroll
        for (int nt = 0; nt < 4; nt++) {
            const int c = n0 + wn * 32 + nt * 8 + (lane & 3) * 2;
            const float bv0 = __ldg(bias + c), bv1 = __ldg(bias + c + 1);
#pragma unroll
            for (int hh = 0; hh < 2; hh++) {
                const int r = r0 + hh * 8;
                const int b = r >> 11, n = r & (N_ - 1);
                const size_t idx = ((size_t)((b * NH + h) * N_ + n)) * D + c;
                store_pair_hilo(dh, dl, idx,
                                acc[mt][nt][2 * hh + 0] + bv0,
                                acc[mt][nt][2 * hh + 1] + bv1);
            }
        }
    }
}

// ---------------------------------------------------------------------------
// 2) E = exp(Q K^T / 16) : grid (16, 16, 24) -> fp32 g_S
//    (no max subtraction: |s| <= |q||k|/16 ~ 5.3, exp safe in fp32;
//     exp here is free under s_tc's tensor-idle slack)
// ---------------------------------------------------------------------------
__global__ void __launch_bounds__(256, 2) s_tc_kernel()
{
    extern __shared__ char smem[];
    const int bh = blockIdx.z;
    const int m0 = blockIdx.y * 128;
    const int n0 = blockIdx.x * 128;

    const __nv_bfloat16* Ah = g_Qh + ((size_t)bh * N_ + m0) * D;
    const __nv_bfloat16* Al = g_Ql + ((size_t)bh * N_ + m0) * D;
    const __nv_bfloat16* Bh = g_Kh + ((size_t)bh * N_ + n0) * D;
    const __nv_bfloat16* Bl = g_Kl + ((size_t)bh * N_ + n0) * D;

    float acc[4][4][4] = {};
    gemm_ml(Ah, Al, Bh, Bl, D, D, D, acc, smem);

    const int lane = threadIdx.x & 31, wid = threadIdx.x >> 5;
    const int wm = wid & 1, wn = wid >> 1;
#pragma unroll
    for (int mt = 0; mt < 4; mt++) {
        const int r0 = m0 + wm * 64 + mt * 16 + (lane >> 2);
#pragma unroll
        for (int nt = 0; nt < 4; nt++) {
            const int c = n0 + wn * 32 + nt * 8 + (lane & 3) * 2;
#pragma unroll
            for (int hh = 0; hh < 2; hh++) {
                const int r = r0 + hh * 8;
                float2 o;
                o.x = __expf(acc[mt][nt][2 * hh + 0] * 0.0625f);
                o.y = __expf(acc[mt][nt][2 * hh + 1] * 0.0625f);
                *reinterpret_cast<float2*>(g_S + ((size_t)bh * N_ + r) * N_ + c) = o;
            }
        }
    }
}

// ---------------------------------------------------------------------------
// 3) Fused PV : grid (2, 16, 24), 256 thr, 115712 B smem.
// O = (E / rowsum(E)) @ V with E = exp(S/16) already computed by s_tc.
// Streams E fp32 chunks (128x32), splits to bf16 hi/lo in smem (convert
// phase has NO exp — pure load/split/store), rowsums per-thread, 1/sum in
// epilogue.  SMEM: E 3x16K | Ph 8K | Pl 8K | V 3x16K | rowsum 1K.
// Per-half ownership: wm=0 warps convert+consume rows 0-63 (named bar 1),
// wm=1 rows 64-127 (named bar 2); one __syncthreads per chunk.
// ---------------------------------------------------------------------------
#define PV_S0   0u
#define PV_PH   49152u
#define PV_PL   57344u
#define PV_V0   65536u
#define PV_RS   114688u
#define PV_SMEM 115712

__global__ void __launch_bounds__(256, 2) pv_fused_kernel()
{
    extern __shared__ char smem[];
    const uint32_t sb = smem_u32(smem);
    const int bh = blockIdx.z;
    const int m0 = blockIdx.y * 128;
    const int n0 = blockIdx.x * 128;     // d-offset
    const int b = bh / 3, h = bh % 3;

    const int tid  = threadIdx.x;
    const int lane = tid & 31;
    const int wid  = tid >> 5;
    const int wm   = wid & 1;
    const int wn   = wid >> 1;

    // MMA addressing (A from P-buf, non-trans; B from V, trans)
    const int rA   = wm * 64 + (lane & 15);
    const int qa   = lane >> 4;
    const int swA2 = (rA >> 1) & 3;
    const int kB   = (lane & 7) + (((lane >> 3) & 1) << 3);
    const int gB   = (wn * 32 + ((lane >> 4) << 3)) >> 3;

    // Convert-role mapping: local id within wm-half
    const int l_cv = ((wid >> 1) << 5) | lane;   // 0..127
    const int r_cv = wm * 64 + (l_cv >> 1);      // row 0..127
    const int h_cv = l_cv & 1;                   // col-half of 32 (16 each)

    const float* Ebase = g_S + ((size_t)bh * N_ + m0) * N_;
    const __nv_bfloat16* Vhb = g_Vh + (size_t)bh * N_ * D + n0;
    const __nv_bfloat16* Vlb = g_Vl + (size_t)bh * N_ * D + n0;

    const int nc = N_ >> 5;   // 64 chunks of 32 tokens

    auto load_chunk = [&](int c) {
        const uint32_t ss = sb + PV_S0 + (uint32_t)(c % 3) * 16384u;
        const uint32_t vs = sb + PV_V0 + (uint32_t)(c % 3) * 16384u;
        const int k0 = c << 5;
#pragma unroll
        for (int i = 0; i < 4; i++) {                 // E: 128 rows x 8 granules
            int f = tid + i * 256, rr = f >> 3, cg = f & 7;
            uint32_t dst = ss + (uint32_t)(rr * 128 + ((cg ^ (rr & 7)) << 4));
            CP16(dst, Ebase + (size_t)rr * N_ + k0 + cg * 4);
        }
#pragma unroll
        for (int i = 0; i < 2; i++) {                 // V: 32 k-rows x 16 groups
            int f = tid + i * 256, kr = f >> 4, g = f & 15;
            uint32_t sw = (uint32_t)(kr * 256 + ((g ^ (kr & 7)) << 4));
            CP16(vs + sw,         Vhb + (size_t)(k0 + kr) * D + g * 8);
            CP16(vs + 8192u + sw, Vlb + (size_t)(k0 + kr) * D + g * 8);
        }
        CP_COMMIT();
    };

    load_chunk(0);
    load_chunk(1);

    float acc[4][4][4] = {};
    float part = 0.f;

    for (int c = 0; c < nc; c++) {
        if (c + 1 < nc) { CP_WAIT_1(); } else { CP_WAIT_0(); }
        __syncthreads();
        if (c + 2 < nc) load_chunk(c + 2);

        // ---- convert own half: split E (already exp'd) to Ph/Pl ----
        {
            const char* srow = smem + (size_t)(c % 3) * 16384 + (size_t)r_cv * 128;
#pragma unroll
            for (int j = 0; j < 4; j++) {
                const int cg = h_cv * 4 + j;
                float4 v = *reinterpret_cast<const float4*>(
                    srow + ((cg ^ (r_cv & 7)) << 4));
                part += (v.x + v.y) + (v.z + v.w);
                uint32_t u0 = __float_as_uint(v.x), u1 = __float_as_uint(v.y);
                uint32_t u2 = __float_as_uint(v.z), u3 = __float_as_uint(v.w);
                uint32_t h01 = (u0 >> 16) | (u1 & 0xffff0000u);
                uint32_t h23 = (u2 >> 16) | (u3 & 0xffff0000u);
                float l0 = v.x - __uint_as_float(u0 & 0xffff0000u);
                float l1 = v.y - __uint_as_float(u1 & 0xffff0000u);
                float l2 = v.z - __uint_as_float(u2 & 0xffff0000u);
                float l3 = v.w - __uint_as_float(u3 & 0xffff0000u);
                const int g = 2 * h_cv + (j >> 1);
                uint32_t off = (uint32_t)(r_cv * 64 +
                               ((g ^ ((r_cv >> 1) & 3)) << 4) + (j & 1) * 8);
                *reinterpret_cast<uint2*>(smem + PV_PH + off) =
                    make_uint2(h01, h23);
                *reinterpret_cast<uint2*>(smem + PV_PL + off) =
                    make_uint2(pack2(l0, l1), pack2(l2, l3));
            }
        }
        asm volatile("bar.sync %0, 128;" :: "r"(1 + wm) : "memory");

        // ---- MMA: A = P-buf (own half rows), B = V slot (trans) ----
        const uint32_t stB  = sb + PV_V0 + (uint32_t)(c % 3) * 16384u;
        const uint32_t stBl = stB + 8192u;
        const uint32_t pH = sb + PV_PH, pL = sb + PV_PL;
#pragma unroll
        for (int kk = 0; kk < 2; kk++) {
            uint32_t bhf[2][4], blf[2][4];
            const int k = kk * 16 + kB;
#pragma unroll
            for (int nt2 = 0; nt2 < 2; nt2++) {
                uint32_t ro = (uint32_t)(k * 256 + (((gB + nt2 * 2) ^ (k & 7)) << 4));
                LDSM_X4_T(bhf[nt2], stB  + ro);
                LDSM_X4_T(blf[nt2], stBl + ro);
            }
            const uint32_t aoff = (uint32_t)(((2 * kk + qa) ^ swA2) << 4);
#pragma unroll
            for (int mt = 0; mt < 4; mt++) {
                uint32_t ahf[4], alf[4];
                uint32_t ro = (uint32_t)((rA + mt * 16) * 64) + aoff;
                LDSM_X4(ahf, pH + ro);
                LDSM_X4(alf, pL + ro);
#pragma unroll
                for (int nt = 0; nt < 4; nt++) {
                    const int n2 = nt >> 1, hi = (nt & 1) * 2;
                    MMA16816(acc[mt][nt], ahf, bhf[n2][hi], bhf[n2][hi + 1]);
                    MMA16816(acc[mt][nt], ahf, blf[n2][hi], blf[n2][hi + 1]);
                    MMA16816(acc[mt][nt], alf, bhf[n2][hi], bhf[n2][hi + 1]);
                }
            }
        }
    }

    // ---- rowsums -> smem, then normalize + store ----
    float* rs = reinterpret_cast<float*>(smem + PV_RS);
    rs[r_cv * 2 + h_cv] = part;
    __syncthreads();

#pragma unroll
    for (int mt = 0; mt < 4; mt++) {
        const int lr = wm * 64 + mt * 16 + (lane >> 2);
        const float inv0 = 1.0f / (rs[lr * 2] + rs[lr * 2 + 1]);
        const float inv1 = 1.0f / (rs[(lr + 8) * 2] + rs[(lr + 8) * 2 + 1]);
#pragma unroll
        for (int nt = 0; nt < 4; nt++) {
            const int c = n0 + wn * 32 + nt * 8 + (lane & 3) * 2;
#pragma unroll
            for (int hh = 0; hh < 2; hh++) {
                const int r = m0 + lr + hh * 8;
                const float inv = hh ? inv1 : inv0;
                const size_t idx = ((size_t)(b * N_ + r)) * E + h * D + c;
                store_pair_hilo(g_atth, g_attl, idx,
                                acc[mt][nt][2 * hh + 0] * inv,
                                acc[mt][nt][2 * hh + 1] * inv);
            }
        }
    }
}

// ---------------------------------------------------------------------------
// 4) out = att @ W0 + b0 : grid (6, 128) -> fp32 out
// ---------------------------------------------------------------------------
__global__ void __launch_bounds__(256, 2) proj_tc_kernel(
    const float* __restrict__ b0, float* __restrict__ out)
{
    extern __shared__ char smem[];
    const int m0 = blockIdx.y * 128;
    const int n0 = blockIdx.x * 128;

    const __nv_bfloat16* Ah = g_atth + (size_t)m0 * E;
    const __nv_bfloat16* Al = g_attl + (size_t)m0 * E;
    const __nv_bfloat16* Bh = g_W0th + (size_t)n0 * E;
    const __nv_bfloat16* Bl = g_W0tl + (size_t)n0 * E;

    float acc[4][4][4] = {};
    gemm_ml(Ah, Al, Bh, Bl, E, E, E, acc, smem);

    const int lane = threadIdx.x & 31, wid = threadIdx.x >> 5;
    const int wm = wid & 1, wn = wid >> 1;
#pragma unroll
    for (int mt = 0; mt < 4; mt++) {
        const int r0 = m0 + wm * 64 + mt * 16 + (lane >> 2);
#pragma unroll
        for (int nt = 0; nt < 4; nt++) {
            const int c = n0 + wn * 32 + nt * 8 + (lane & 3) * 2;
            const float bv0 = __ldg(b0 + c), bv1 = __ldg(b0 + c + 1);
#pragma unroll
            for (int hh = 0; hh < 2; hh++) {
                const int r = r0 + hh * 8;
                float2 o;
                o.x = acc[mt][nt][2 * hh + 0] + bv0;
                o.y = acc[mt][nt][2 * hh + 1] + bv1;
                *reinterpret_cast<float2*>(out + (size_t)r * E + c) = o;
            }
        }
    }
}

// ---------------------------------------------------------------------------
extern "C" void kernel_launch(void* const* d_in, const int* in_sizes, int n_in,
                              void* d_out, int out_size)
{
    const float* x  = (const float*)d_in[0];
    const float* Wq = (const float*)d_in[1];
    const float* bq = (const float*)d_in[2];
    const float* Wk = (const float*)d_in[3];
    const float* bk = (const float*)d_in[4];
    const float* Wv = (const float*)d_in[5];
    const float* bv = (const float*)d_in[6];
    const float* W0 = (const float*)d_in[7];
    const float* b0 = (const float*)d_in[8];
    float* out = (float*)d_out;

    cudaFuncSetAttribute(qkv_tc_kernel,   cudaFuncAttributeMaxDynamicSharedMemorySize, GSMEM_BYTES);
    cudaFuncSetAttribute(s_tc_kernel,     cudaFuncAttributeMaxDynamicSharedMemorySize, GSMEM_BYTES);
    cudaFuncSetAttribute(pv_fused_kernel, cudaFuncAttributeMaxDynamicSharedMemorySize, PV_SMEM);
    cudaFuncSetAttribute(proj_tc_kernel,  cudaFuncAttributeMaxDynamicSharedMemorySize, GSMEM_BYTES);

    convert_x_kernel<<<(M_TOT * E / 4) / 256, 256>>>(x);
    convert_w_kernel<<<(9 * D * E + E * E) / 256, 256>>>(Wq, Wk, Wv, W0);

    qkv_tc_kernel<<<dim3(2, 128, 9), 256, GSMEM_BYTES>>>(bq, bk, bv);
    s_tc_kernel<<<dim3(16, 16, BH_), 256, GSMEM_BYTES>>>();
    pv_fused_kernel<<<dim3(2, 16, BH_), 256, PV_SMEM>>>();
    proj_tc_kernel<<<dim3(6, 128), 256, GSMEM_BYTES>>>(b0, out);
}